// round 14
// baseline (speedup 1.0000x reference)
#include <cuda_runtime.h>
#include <cuda_bf16.h>
#include <cstdint>
#include <math.h>

#define D_DIM 1024
#define B_DIM 2
#define S_DIM 1024
#define NROWS (B_DIM * S_DIM)   // 2048
#define L_DIM 2
#define V_DIM 32000

// GEMM smem geometry (floats), 2-stage pipeline, 128x128 tiles
#define A_STRIDE 36
#define B_STRIDE 136
#define A_TILE (128 * A_STRIDE)
#define B_TILE (32 * B_STRIDE)
#define GEMM_SMEM_BYTES (2 * (A_TILE + B_TILE) * 4)   // 71680

// ---------------- scratch (device globals; no allocation allowed) ----------------
__device__ float g_x[NROWS * D_DIM];
__device__ float g_q[NROWS * D_DIM];
__device__ float g_k[NROWS * D_DIM];
__device__ float g_v[NROWS * D_DIM];
__device__ float g_o[NROWS * D_DIM];
__device__ float g_beta[NROWS];
__device__ float g_qk[NROWS];

// ---------------- helpers ----------------
__device__ __forceinline__ float2 ffma2(float2 a, float2 b, float2 c) {
    float2 d;
    asm("fma.rn.f32x2 %0, %1, %2, %3;"
        : "=l"(reinterpret_cast<unsigned long long &>(d))
        : "l"(reinterpret_cast<unsigned long long &>(a)),
          "l"(reinterpret_cast<unsigned long long &>(b)),
          "l"(reinterpret_cast<unsigned long long &>(c)));
    return d;
}

// m16n8k16 bf16 mma (sm_80+ baseline ISA — no 'a' features needed)
__device__ __forceinline__ void mma_bf16(float* c, const uint32_t* a, const uint32_t* b) {
    asm volatile(
        "mma.sync.aligned.m16n8k16.row.col.f32.bf16.bf16.f32 "
        "{%0,%1,%2,%3}, {%4,%5,%6,%7}, {%8,%9}, {%0,%1,%2,%3};"
        : "+f"(c[0]), "+f"(c[1]), "+f"(c[2]), "+f"(c[3])
        : "r"(a[0]), "r"(a[1]), "r"(a[2]), "r"(a[3]), "r"(b[0]), "r"(b[1]));
}

// pack two fp32 into bf16x2 (f0 -> low half = first k element), plus residual pair
__device__ __forceinline__ void split_pair(float f0, float f1, uint32_t& hi, uint32_t& lo) {
    __nv_bfloat162 h2 = __floats2bfloat162_rn(f0, f1);   // .x (low) = f0
    float r0 = f0 - __low2float(h2);
    float r1 = f1 - __high2float(h2);
    __nv_bfloat162 l2 = __floats2bfloat162_rn(r0, r1);
    hi = *reinterpret_cast<uint32_t*>(&h2);
    lo = *reinterpret_cast<uint32_t*>(&l2);
}

__device__ __forceinline__ void cp16(void* dst, const void* src) {
    uint32_t d = (uint32_t)__cvta_generic_to_shared(dst);
    asm volatile("cp.async.cg.shared.global [%0], [%1], 16;" :: "r"(d), "l"(src));
}
__device__ __forceinline__ void cp_commit() {
    asm volatile("cp.async.commit_group;");
}

__device__ __forceinline__ float silu1(float x) { return x / (1.f + expf(-x)); }

__device__ __forceinline__ float blockReduceSum(float v, float* sh) {
    #pragma unroll
    for (int o = 16; o; o >>= 1) v += __shfl_xor_sync(0xffffffffu, v, o);
    int w = threadIdx.x >> 5;
    if ((threadIdx.x & 31) == 0) sh[w] = v;
    __syncthreads();
    if (threadIdx.x == 0) {
        float s = sh[0];
        #pragma unroll
        for (int i = 1; i < 8; i++) s += sh[i];
        sh[0] = s;
    }
    __syncthreads();
    return sh[0];
}

// ---------------- embedding gather ----------------
__global__ void embed_k(const int* __restrict__ tokens, const float* __restrict__ emb,
                        float* __restrict__ x) {
    int row = blockIdx.x;
    int tok = tokens[row];
    ((float4*)(x + (size_t)row * D_DIM))[threadIdx.x] =
        ((const float4*)(emb + (size_t)tok * D_DIM))[threadIdx.x];
}

// ---------------- GEMM core 128x128 (2-stage cp.async, bf16 hi/lo 3-product) ----------------
// 8 warps (2x4), warp tile 64x32. Per 32-K tile: 2 ksteps of m16n8k16.
// Accuracy ~2^-16 relative (hh+hl+lh, ll dropped). smem holds raw fp32.
template <bool SILU>
__device__ __forceinline__ void gemm_body(
    const float* __restrict__ A, const float* __restrict__ B, float* __restrict__ C,
    int N, int K, int bm, int bn, float* sm) {

    int tid  = threadIdx.x;
    int warp = tid >> 5, lane = tid & 31;
    int wm = warp >> 2, wn = warp & 3;
    int g = lane >> 2, tg = lane & 3;

    float acc[4][4][4];
    #pragma unroll
    for (int mt = 0; mt < 4; mt++)
        #pragma unroll
        for (int nt = 0; nt < 4; nt++)
            #pragma unroll
            for (int r = 0; r < 4; r++) acc[mt][nt][r] = 0.f;

    const float* Ab = A + (size_t)(bm * 128) * K;
    const float* Bb = B + bn * 128;

    int arow = tid >> 3;
    int acol = (tid & 7) * 4;
    int brow = tid >> 5;
    int bcol = (tid & 31) * 4;

    const int NT = K >> 5;

    {   // prologue: prefetch tile 0
        float* A0 = sm;
        float* B0 = sm + 2 * A_TILE;
        #pragma unroll
        for (int p = 0; p < 4; p++) {
            int r = arow + p * 32;
            cp16(&A0[r * A_STRIDE + acol], Ab + (size_t)r * K + acol);
        }
        #pragma unroll
        for (int p = 0; p < 4; p++) {
            int r = brow + p * 8;
            cp16(&B0[r * B_STRIDE + bcol], Bb + (size_t)r * N + bcol);
        }
        cp_commit();
    }

    for (int t = 0; t < NT; t++) {
        float* Ac = sm + (t & 1) * A_TILE;
        float* Bc = sm + 2 * A_TILE + (t & 1) * B_TILE;
        if (t + 1 < NT) {
            float* An = sm + ((t + 1) & 1) * A_TILE;
            float* Bn = sm + 2 * A_TILE + ((t + 1) & 1) * B_TILE;
            int k0 = (t + 1) * 32;
            #pragma unroll
            for (int p = 0; p < 4; p++) {
                int r = arow + p * 32;
                cp16(&An[r * A_STRIDE + acol], Ab + (size_t)r * K + k0 + acol);
            }
            #pragma unroll
            for (int p = 0; p < 4; p++) {
                int r = brow + p * 8;
                cp16(&Bn[r * B_STRIDE + bcol], Bb + (size_t)(k0 + r) * N + bcol);
            }
            cp_commit();
            asm volatile("cp.async.wait_group 1;");
        } else {
            asm volatile("cp.async.wait_group 0;");
        }
        __syncthreads();

        #pragma unroll
        for (int kk = 0; kk < 2; kk++) {          // 2 x k16 per 32-wide tile
            // B fragments: b0 = (k = 2tg,2tg+1, col), b1 = (k+8, col)
            uint32_t bh[4][2], bl[4][2];
            #pragma unroll
            for (int nt = 0; nt < 4; nt++) {
                int col = wn * 32 + nt * 8 + g;
                #pragma unroll
                for (int h = 0; h < 2; h++) {
                    int krow = kk * 16 + tg * 2 + h * 8;
                    float f0 = Bc[krow * B_STRIDE + col];
                    float f1 = Bc[(krow + 1) * B_STRIDE + col];
                    split_pair(f0, f1, bh[nt][h], bl[nt][h]);
                }
            }
            #pragma unroll
            for (int mt = 0; mt < 4; mt++) {
                // A fragments: a0=(g,2tg..), a1=(g+8,..), a2=(g,2tg+8..), a3=(g+8,..)
                int rbase = (wm * 64 + mt * 16) * A_STRIDE + kk * 16 + tg * 2;
                float2 p0 = *(float2*)&Ac[rbase + g * A_STRIDE];
                float2 p1 = *(float2*)&Ac[rbase + (g + 8) * A_STRIDE];
                float2 p2 = *(float2*)&Ac[rbase + g * A_STRIDE + 8];
                float2 p3 = *(float2*)&Ac[rbase + (g + 8) * A_STRIDE + 8];
                uint32_t ah[4], al[4];
                split_pair(p0.x, p0.y, ah[0], al[0]);
                split_pair(p1.x, p1.y, ah[1], al[1]);
                split_pair(p2.x, p2.y, ah[2], al[2]);
                split_pair(p3.x, p3.y, ah[3], al[3]);
                #pragma unroll
                for (int nt = 0; nt < 4; nt++) {
                    mma_bf16(acc[mt][nt], ah, bl[nt]);
                    mma_bf16(acc[mt][nt], al, bh[nt]);
                    mma_bf16(acc[mt][nt], ah, bh[nt]);
                }
            }
        }
        __syncthreads();
    }

    int row0 = bm * 128 + wm * 64;
    int col0 = bn * 128 + wn * 32;
    #pragma unroll
    for (int mt = 0; mt < 4; mt++)
        #pragma unroll
        for (int nt = 0; nt < 4; nt++) {
            int row = row0 + mt * 16 + g;
            int col = col0 + nt * 8 + tg * 2;
            float v0 = acc[mt][nt][0], v1 = acc[mt][nt][1];
            float v2 = acc[mt][nt][2], v3 = acc[mt][nt][3];
            if (SILU) { v0 = silu1(v0); v1 = silu1(v1); v2 = silu1(v2); v3 = silu1(v3); }
            *(float2*)(C + (size_t)row * N + col) = make_float2(v0, v1);
            *(float2*)(C + (size_t)(row + 8) * N + col) = make_float2(v2, v3);
        }
}

// standalone GEMM
__global__ __launch_bounds__(256, 2) void gemm_mm(
    const float* __restrict__ A, const float* __restrict__ B, float* __restrict__ C,
    int M, int N, int K) {
    extern __shared__ float sm[];
    gemm_body<false>(A, B, C, N, K, blockIdx.y, blockIdx.x, sm);
}

// fused QKV: grid z selects weight/output; z==2 (V) applies silu in epilogue
__global__ __launch_bounds__(256, 2) void gemm_qkv(
    const float* __restrict__ X,
    const float* __restrict__ Wq, const float* __restrict__ Wk, const float* __restrict__ Wv,
    float* __restrict__ Q, float* __restrict__ Ko, float* __restrict__ Vo) {
    extern __shared__ float sm[];
    int z = blockIdx.z;
    const float* B = (z == 0) ? Wq : (z == 1) ? Wk : Wv;
    float* C = (z == 0) ? Q : (z == 1) ? Ko : Vo;
    if (z == 2)
        gemm_body<true>(X, B, C, D_DIM, D_DIM, blockIdx.y, blockIdx.x, sm);
    else
        gemm_body<false>(X, B, C, D_DIM, D_DIM, blockIdx.y, blockIdx.x, sm);
}

// ---------------- fused prep: beta, silu+l2norm(q), silu+l2norm(k), qk dot ----------------
__global__ void prep_k(const float* __restrict__ x, const float* __restrict__ wb,
                       float* __restrict__ q, float* __restrict__ k,
                       float* __restrict__ beta, float* __restrict__ qk) {
    __shared__ float sh0[8], sh1[8], sh2[8], sh3[8];
    int row = blockIdx.x, tid = threadIdx.x;

    const float4* xr = (const float4*)(x + (size_t)row * D_DIM);
    const float4* wr = (const float4*)wb;
    float4 xv = xr[tid], wv = wr[tid];
    float bd = xv.x * wv.x + xv.y * wv.y + xv.z * wv.z + xv.w * wv.w;
    float bsum = blockReduceSum(bd, sh0);
    if (tid == 0) beta[row] = 1.f / (1.f + expf(-bsum));

    float4* qr = (float4*)(q + (size_t)row * D_DIM);
    float4 a = qr[tid];
    a.x = silu1(a.x); a.y = silu1(a.y); a.z = silu1(a.z); a.w = silu1(a.w);
    float qs = a.x * a.x + a.y * a.y + a.z * a.z + a.w * a.w;
    float qtot = blockReduceSum(qs, sh1);
    float qrs = rsqrtf(qtot + 1e-6f);
    a.x *= qrs; a.y *= qrs; a.z *= qrs; a.w *= qrs;
    qr[tid] = a;

    float4* kr = (float4*)(k + (size_t)row * D_DIM);
    float4 b = kr[tid];
    b.x = silu1(b.x); b.y = silu1(b.y); b.z = silu1(b.z); b.w = silu1(b.w);
    float ks = b.x * b.x + b.y * b.y + b.z * b.z + b.w * b.w;
    float ktot = blockReduceSum(ks, sh2);
    float krs = rsqrtf(ktot + 1e-6f);
    b.x *= krs; b.y *= krs; b.z *= krs; b.w *= krs;
    kr[tid] = b;

    float d = a.x * b.x + a.y * b.y + a.z * b.z + a.w * b.w;
    float dtot = blockReduceSum(d, sh3);
    if (tid == 0) qk[row] = dtot;
}

// ---------------- rmsnorm in place ----------------
__global__ void rmsnorm_k(float* __restrict__ x, const float* __restrict__ w) {
    __shared__ float sh[8];
    float4* xr = (float4*)(x + (size_t)blockIdx.x * D_DIM);
    float4 a = xr[threadIdx.x];
    float ss = a.x * a.x + a.y * a.y + a.z * a.z + a.w * a.w;
    float tot = blockReduceSum(ss, sh);
    float r = rsqrtf(tot * (1.f / D_DIM) + 1e-5f);
    float4 wv = ((const float4*)w)[threadIdx.x];
    a.x *= r * wv.x; a.y *= r * wv.y; a.z *= r * wv.z; a.w *= r * wv.w;
    xr[threadIdx.x] = a;
}

// ---------------- layernorm in place ----------------
__global__ void layernorm_k(float* __restrict__ x, const float* __restrict__ gg,
                            const float* __restrict__ bb) {
    __shared__ float sh1[8];
    __shared__ float sh2[8];
    float4* xr = (float4*)(x + (size_t)blockIdx.x * D_DIM);
    float4 a = xr[threadIdx.x];
    float s  = a.x + a.y + a.z + a.w;
    float ss = a.x * a.x + a.y * a.y + a.z * a.z + a.w * a.w;
    float S  = blockReduceSum(s, sh1);
    float SS = blockReduceSum(ss, sh2);
    float mu  = S * (1.f / D_DIM);
    float var = SS * (1.f / D_DIM) - mu * mu;
    float r = rsqrtf(var + 1e-5f);
    float4 gv = ((const float4*)gg)[threadIdx.x];
    float4 bv = ((const float4*)bb)[threadIdx.x];
    a.x = (a.x - mu) * r * gv.x + bv.x;
    a.y = (a.y - mu) * r * gv.y + bv.y;
    a.z = (a.z - mu) * r * gv.z + bv.z;
    a.w = (a.w - mu) * r * gv.w + bv.w;
    xr[threadIdx.x] = a;
}

// ---------------- delta-rule scan (R4 version, known good) ----------------
__global__ __launch_bounds__(256) void delta_scan(
    const float* __restrict__ q, const float* __restrict__ k,
    const float* __restrict__ v, const float* __restrict__ beta,
    const float* __restrict__ qk, float* __restrict__ o) {
    __shared__ float sk[1024];
    __shared__ float sq[1024];
    __shared__ float part[16 * 132];
    __shared__ float tot[16];

    int tid = threadIdx.x;
    int b = blockIdx.x >> 7;
    int ebase = (blockIdx.x & 127) * 8;
    int cg = tid >> 7;
    int rg = tid & 127;
    int d0 = rg * 8;
    int e0 = ebase + cg * 4;

    float2 S[4][4];
    #pragma unroll
    for (int r = 0; r < 4; r++)
        #pragma unroll
        for (int c = 0; c < 4; c++) S[r][c] = make_float2(0.f, 0.f);

    const float* qb = q + (size_t)b * S_DIM * D_DIM;
    const float* kb = k + (size_t)b * S_DIM * D_DIM;
    const float* vb = v + (size_t)b * S_DIM * D_DIM;
    const float* betab = beta + b * S_DIM;
    const float* qkb   = qk + b * S_DIM;
    float* ob = o + (size_t)b * S_DIM * D_DIM;

    int gj = tid >> 4, sl = tid & 15;

    for (int t = 0; t < S_DIM; t++) {
        ((float4*)sk)[tid] = ((const float4*)(kb + (size_t)t * D_DIM))[tid];
        ((float4*)sq)[tid] = ((const float4*)(qb + (size_t)t * D_DIM))[tid];
        __syncthreads();

        float4 kA = *(float4*)(sk + d0);
        float4 kB = *(float4*)(sk + d0 + 4);
        float4 qA = *(float4*)(sq + d0);
        float4 qB = *(float4*)(sq + d0 + 4);
        float2 kv[4] = {{kA.x, kA.y}, {kA.z, kA.w}, {kB.x, kB.y}, {kB.z, kB.w}};
        float2 qv[4] = {{qA.x, qA.y}, {qA.z, qA.w}, {qB.x, qB.y}, {qB.z, qB.w}};

        float2 ks2[4], qs2[4];
        #pragma unroll
        for (int c = 0; c < 4; c++) { ks2[c] = make_float2(0.f, 0.f); qs2[c] = make_float2(0.f, 0.f); }
        #pragma unroll
        for (int c = 0; c < 4; c++)
            #pragma unroll
            for (int r = 0; r < 4; r++) {
                ks2[c] = ffma2(kv[r], S[r][c], ks2[c]);
                qs2[c] = ffma2(qv[r], S[r][c], qs2[c]);
            }
        #pragma unroll
        for (int c = 0; c < 4; c++) {
            part[(cg * 8 + c) * 132 + rg]     = ks2[c].x + ks2[c].y;
            part[(cg * 8 + 4 + c) * 132 + rg] = qs2[c].x + qs2[c].y;
        }
        __syncthreads();

        {
            const float* pg = part + gj * 132;
            float ps = 0.f;
            #pragma unroll
            for (int i = 0; i < 8; i++) ps += pg[sl + 16 * i];
            #pragma unroll
            for (int off = 8; off; off >>= 1) ps += __shfl_down_sync(0xffffffffu, ps, off, 16);
            if (sl == 0) tot[gj] = ps;
        }
        __syncthreads();

        float be  = betab[t];
        float qkt = qkb[t];
        float cc[4];
        #pragma unroll
        for (int c = 0; c < 4; c++) {
            float ksv = tot[cg * 8 + c];
            float vv  = __ldg(vb + (size_t)t * D_DIM + e0 + c);
            cc[c] = be * (vv - ksv);
            if (rg == 0) ob[(size_t)t * D_DIM + e0 + c] = tot[cg * 8 + 4 + c] + qkt * cc[c];
        }
        #pragma unroll
        for (int c = 0; c < 4; c++) {
            float2 c2 = make_float2(cc[c], cc[c]);
            #pragma unroll
            for (int r = 0; r < 4; r++) S[r][c] = ffma2(kv[r], c2, S[r][c]);
        }
        __syncthreads();
    }
}

// ---------------- host orchestration ----------------
extern "C" void kernel_launch(void* const* d_in, const int* in_sizes, int n_in,
                              void* d_out, int out_size) {
    const int*   tokens = (const int*)d_in[0];
    const float* emb    = (const float*)d_in[1];
    const float* Wq     = (const float*)d_in[2];
    const float* Wk     = (const float*)d_in[3];
    const float* Wv     = (const float*)d_in[4];
    const float* Wb     = (const float*)d_in[5];
    const float* Wo     = (const float*)d_in[6];
    const float* rms_w  = (const float*)d_in[7];
    const float* ln_g   = (const float*)d_in[8];
    const float* ln_b   = (const float*)d_in[9];
    const float* head_w = (const float*)d_in[10];
    float* out = (float*)d_out;

    float *x, *qb, *kb, *vb, *ob, *betab, *qkb;
    cudaGetSymbolAddress((void**)&x, g_x);
    cudaGetSymbolAddress((void**)&qb, g_q);
    cudaGetSymbolAddress((void**)&kb, g_k);
    cudaGetSymbolAddress((void**)&vb, g_v);
    cudaGetSymbolAddress((void**)&ob, g_o);
    cudaGetSymbolAddress((void**)&betab, g_beta);
    cudaGetSymbolAddress((void**)&qkb, g_qk);

    cudaFuncSetAttribute(gemm_mm,  cudaFuncAttributeMaxDynamicSharedMemorySize, GEMM_SMEM_BYTES);
    cudaFuncSetAttribute(gemm_qkv, cudaFuncAttributeMaxDynamicSharedMemorySize, GEMM_SMEM_BYTES);

    embed_k<<<NROWS, 256>>>(tokens, emb, x);

    dim3 g1(D_DIM / 128, NROWS / 128);
    dim3 gqkv(D_DIM / 128, NROWS / 128, 3);
    for (int l = 0; l < L_DIM; l++) {
        const float* wq = Wq + (size_t)l * D_DIM * D_DIM;
        const float* wk = Wk + (size_t)l * D_DIM * D_DIM;
        const float* wv = Wv + (size_t)l * D_DIM * D_DIM;
        const float* wb = Wb + (size_t)l * D_DIM;
        const float* wo = Wo + (size_t)l * D_DIM * D_DIM;
        const float* rw = rms_w + (size_t)l * D_DIM;

        gemm_qkv<<<gqkv, 256, GEMM_SMEM_BYTES>>>(x, wq, wk, wv, qb, kb, vb);
        prep_k<<<NROWS, 256>>>(x, wb, qb, kb, betab, qkb);
        delta_scan<<<256, 256>>>(qb, kb, vb, betab, qkb, ob);
        rmsnorm_k<<<NROWS, 256>>>(ob, rw);
        gemm_mm<<<g1, 256, GEMM_SMEM_BYTES>>>(ob, wo, x, NROWS, D_DIM, D_DIM);
    }
    layernorm_k<<<NROWS, 256>>>(x, ln_g, ln_b);

    dim3 g2(V_DIM / 128, NROWS / 128);   // (250,16)
    gemm_mm<<<g2, 256, GEMM_SMEM_BYTES>>>(x, head_w, out, NROWS, V_DIM, D_DIM);
}

// round 15
// speedup vs baseline: 1.1872x; 1.1872x over previous
#include <cuda_runtime.h>
#include <cuda_bf16.h>
#include <cuda_fp16.h>
#include <cstdint>
#include <math.h>

#define D_DIM 1024
#define B_DIM 2
#define S_DIM 1024
#define NROWS (B_DIM * S_DIM)   // 2048
#define L_DIM 2
#define V_DIM 32000

// GEMM smem geometry (floats), 2-stage pipeline, 128x128 tiles
#define A_STRIDE 36
#define B_STRIDE 136
#define A_TILE (128 * A_STRIDE)
#define B_TILE (32 * B_STRIDE)
#define GEMM_SMEM_BYTES (2 * (A_TILE + B_TILE) * 4)   // 71680

// fp16 head GEMM geometry: K-tile 64, stride 72 halves (conflict-free: 36g+tg distinct mod 32)
#define HKT 64
#define H_ST 72
#define H_MAT (128 * H_ST)                 // halves per matrix per stage
#define HEAD_SMEM_BYTES (2 * 2 * H_MAT * 2)  // 2 stages x (A+B) x 2B = 73728

// ---------------- scratch (device globals; no allocation allowed) ----------------
__device__ float g_x[NROWS * D_DIM];
__device__ float g_q[NROWS * D_DIM];
__device__ float g_k[NROWS * D_DIM];
__device__ float g_v[NROWS * D_DIM];
__device__ float g_o[NROWS * D_DIM];
__device__ float g_beta[NROWS];
__device__ float g_qk[NROWS];
__device__ __half g_xh[NROWS * D_DIM];                 // ln(x) fp16
__device__ __half g_wt[(size_t)V_DIM * D_DIM];         // head_w^T fp16 [N][K]

// ---------------- helpers ----------------
__device__ __forceinline__ float2 ffma2(float2 a, float2 b, float2 c) {
    float2 d;
    asm("fma.rn.f32x2 %0, %1, %2, %3;"
        : "=l"(reinterpret_cast<unsigned long long &>(d))
        : "l"(reinterpret_cast<unsigned long long &>(a)),
          "l"(reinterpret_cast<unsigned long long &>(b)),
          "l"(reinterpret_cast<unsigned long long &>(c)));
    return d;
}

__device__ __forceinline__ void mma_bf16(float* c, const uint32_t* a, const uint32_t* b) {
    asm volatile(
        "mma.sync.aligned.m16n8k16.row.col.f32.bf16.bf16.f32 "
        "{%0,%1,%2,%3}, {%4,%5,%6,%7}, {%8,%9}, {%0,%1,%2,%3};"
        : "+f"(c[0]), "+f"(c[1]), "+f"(c[2]), "+f"(c[3])
        : "r"(a[0]), "r"(a[1]), "r"(a[2]), "r"(a[3]), "r"(b[0]), "r"(b[1]));
}

__device__ __forceinline__ void mma_f16(float* c, const uint32_t* a, const uint32_t* b) {
    asm volatile(
        "mma.sync.aligned.m16n8k16.row.col.f32.f16.f16.f32 "
        "{%0,%1,%2,%3}, {%4,%5,%6,%7}, {%8,%9}, {%0,%1,%2,%3};"
        : "+f"(c[0]), "+f"(c[1]), "+f"(c[2]), "+f"(c[3])
        : "r"(a[0]), "r"(a[1]), "r"(a[2]), "r"(a[3]), "r"(b[0]), "r"(b[1]));
}

__device__ __forceinline__ void split_pair(float f0, float f1, uint32_t& hi, uint32_t& lo) {
    __nv_bfloat162 h2 = __floats2bfloat162_rn(f0, f1);
    float r0 = f0 - __low2float(h2);
    float r1 = f1 - __high2float(h2);
    __nv_bfloat162 l2 = __floats2bfloat162_rn(r0, r1);
    hi = *reinterpret_cast<uint32_t*>(&h2);
    lo = *reinterpret_cast<uint32_t*>(&l2);
}

__device__ __forceinline__ void cp16(void* dst, const void* src) {
    uint32_t d = (uint32_t)__cvta_generic_to_shared(dst);
    asm volatile("cp.async.cg.shared.global [%0], [%1], 16;" :: "r"(d), "l"(src));
}
__device__ __forceinline__ void cp_commit() {
    asm volatile("cp.async.commit_group;");
}

__device__ __forceinline__ float silu1(float x) { return x / (1.f + expf(-x)); }

__device__ __forceinline__ float blockReduceSum(float v, float* sh) {
    #pragma unroll
    for (int o = 16; o; o >>= 1) v += __shfl_xor_sync(0xffffffffu, v, o);
    int w = threadIdx.x >> 5;
    if ((threadIdx.x & 31) == 0) sh[w] = v;
    __syncthreads();
    if (threadIdx.x == 0) {
        float s = sh[0];
        #pragma unroll
        for (int i = 1; i < 8; i++) s += sh[i];
        sh[0] = s;
    }
    __syncthreads();
    return sh[0];
}

// ---------------- embedding gather ----------------
__global__ void embed_k(const int* __restrict__ tokens, const float* __restrict__ emb,
                        float* __restrict__ x) {
    int row = blockIdx.x;
    int tok = tokens[row];
    ((float4*)(x + (size_t)row * D_DIM))[threadIdx.x] =
        ((const float4*)(emb + (size_t)tok * D_DIM))[threadIdx.x];
}

// ---------------- transpose head_w -> fp16 Wt[N][K] ----------------
__global__ void transpose_h(const float* __restrict__ W, __half* __restrict__ Wt) {
    __shared__ float tile[32][33];
    int n0 = blockIdx.x * 32, k0 = blockIdx.y * 32;
    int tx = threadIdx.x, ty = threadIdx.y;
    #pragma unroll
    for (int i = ty; i < 32; i += 8)
        tile[i][tx] = W[(size_t)(k0 + i) * V_DIM + n0 + tx];
    __syncthreads();
    #pragma unroll
    for (int i = ty; i < 32; i += 8)
        Wt[(size_t)(n0 + i) * D_DIM + k0 + tx] = __float2half(tile[tx][i]);
}

// ---------------- GEMM core 128x128 (2-stage cp.async, bf16 hi/lo 3-product) ----------------
template <bool SILU>
__device__ __forceinline__ void gemm_body(
    const float* __restrict__ A, const float* __restrict__ B, float* __restrict__ C,
    int N, int K, int bm, int bn, float* sm) {

    int tid  = threadIdx.x;
    int warp = tid >> 5, lane = tid & 31;
    int wm = warp >> 2, wn = warp & 3;
    int g = lane >> 2, tg = lane & 3;

    float acc[4][4][4];
    #pragma unroll
    for (int mt = 0; mt < 4; mt++)
        #pragma unroll
        for (int nt = 0; nt < 4; nt++)
            #pragma unroll
            for (int r = 0; r < 4; r++) acc[mt][nt][r] = 0.f;

    const float* Ab = A + (size_t)(bm * 128) * K;
    const float* Bb = B + bn * 128;

    int arow = tid >> 3;
    int acol = (tid & 7) * 4;
    int brow = tid >> 5;
    int bcol = (tid & 31) * 4;

    const int NT = K >> 5;

    {
        float* A0 = sm;
        float* B0 = sm + 2 * A_TILE;
        #pragma unroll
        for (int p = 0; p < 4; p++) {
            int r = arow + p * 32;
            cp16(&A0[r * A_STRIDE + acol], Ab + (size_t)r * K + acol);
        }
        #pragma unroll
        for (int p = 0; p < 4; p++) {
            int r = brow + p * 8;
            cp16(&B0[r * B_STRIDE + bcol], Bb + (size_t)r * N + bcol);
        }
        cp_commit();
    }

    for (int t = 0; t < NT; t++) {
        float* Ac = sm + (t & 1) * A_TILE;
        float* Bc = sm + 2 * A_TILE + (t & 1) * B_TILE;
        if (t + 1 < NT) {
            float* An = sm + ((t + 1) & 1) * A_TILE;
            float* Bn = sm + 2 * A_TILE + ((t + 1) & 1) * B_TILE;
            int k0 = (t + 1) * 32;
            #pragma unroll
            for (int p = 0; p < 4; p++) {
                int r = arow + p * 32;
                cp16(&An[r * A_STRIDE + acol], Ab + (size_t)r * K + k0 + acol);
            }
            #pragma unroll
            for (int p = 0; p < 4; p++) {
                int r = brow + p * 8;
                cp16(&Bn[r * B_STRIDE + bcol], Bb + (size_t)(k0 + r) * N + bcol);
            }
            cp_commit();
            asm volatile("cp.async.wait_group 1;");
        } else {
            asm volatile("cp.async.wait_group 0;");
        }
        __syncthreads();

        #pragma unroll
        for (int kk = 0; kk < 2; kk++) {
            uint32_t bh[4][2], bl[4][2];
            #pragma unroll
            for (int nt = 0; nt < 4; nt++) {
                int col = wn * 32 + nt * 8 + g;
                #pragma unroll
                for (int h = 0; h < 2; h++) {
                    int krow = kk * 16 + tg * 2 + h * 8;
                    float f0 = Bc[krow * B_STRIDE + col];
                    float f1 = Bc[(krow + 1) * B_STRIDE + col];
                    split_pair(f0, f1, bh[nt][h], bl[nt][h]);
                }
            }
            #pragma unroll
            for (int mt = 0; mt < 4; mt++) {
                int rbase = (wm * 64 + mt * 16) * A_STRIDE + kk * 16 + tg * 2;
                float2 p0 = *(float2*)&Ac[rbase + g * A_STRIDE];
                float2 p1 = *(float2*)&Ac[rbase + (g + 8) * A_STRIDE];
                float2 p2 = *(float2*)&Ac[rbase + g * A_STRIDE + 8];
                float2 p3 = *(float2*)&Ac[rbase + (g + 8) * A_STRIDE + 8];
                uint32_t ah[4], al[4];
                split_pair(p0.x, p0.y, ah[0], al[0]);
                split_pair(p1.x, p1.y, ah[1], al[1]);
                split_pair(p2.x, p2.y, ah[2], al[2]);
                split_pair(p3.x, p3.y, ah[3], al[3]);
                #pragma unroll
                for (int nt = 0; nt < 4; nt++) {
                    mma_bf16(acc[mt][nt], ah, bl[nt]);
                    mma_bf16(acc[mt][nt], al, bh[nt]);
                    mma_bf16(acc[mt][nt], ah, bh[nt]);
                }
            }
        }
        __syncthreads();
    }

    int row0 = bm * 128 + wm * 64;
    int col0 = bn * 128 + wn * 32;
    #pragma unroll
    for (int mt = 0; mt < 4; mt++)
        #pragma unroll
        for (int nt = 0; nt < 4; nt++) {
            int row = row0 + mt * 16 + g;
            int col = col0 + nt * 8 + tg * 2;
            float v0 = acc[mt][nt][0], v1 = acc[mt][nt][1];
            float v2 = acc[mt][nt][2], v3 = acc[mt][nt][3];
            if (SILU) { v0 = silu1(v0); v1 = silu1(v1); v2 = silu1(v2); v3 = silu1(v3); }
            *(float2*)(C + (size_t)row * N + col) = make_float2(v0, v1);
            *(float2*)(C + (size_t)(row + 8) * N + col) = make_float2(v2, v3);
        }
}

__global__ __launch_bounds__(256, 2) void gemm_mm(
    const float* __restrict__ A, const float* __restrict__ B, float* __restrict__ C,
    int M, int N, int K) {
    extern __shared__ float sm[];
    gemm_body<false>(A, B, C, N, K, blockIdx.y, blockIdx.x, sm);
}

__global__ __launch_bounds__(256, 2) void gemm_qkv(
    const float* __restrict__ X,
    const float* __restrict__ Wq, const float* __restrict__ Wk, const float* __restrict__ Wv,
    float* __restrict__ Q, float* __restrict__ Ko, float* __restrict__ Vo) {
    extern __shared__ float sm[];
    int z = blockIdx.z;
    const float* B = (z == 0) ? Wq : (z == 1) ? Wk : Wv;
    float* C = (z == 0) ? Q : (z == 1) ? Ko : Vo;
    if (z == 2)
        gemm_body<true>(X, B, C, D_DIM, D_DIM, blockIdx.y, blockIdx.x, sm);
    else
        gemm_body<false>(X, B, C, D_DIM, D_DIM, blockIdx.y, blockIdx.x, sm);
}

// ---------------- fp16 head GEMM: C[2048,32000] = Xh[M,K] @ Wt[N,K]^T ----------------
// 128x128 tile, K-tile 64, 2-stage cp.async, single-pass fp16 m16n8k16.
// Both operands K-contiguous in smem; frag pairs are packed uint32 LDS (no cvt in hot loop).
__global__ __launch_bounds__(256, 2) void gemm_head_f16(
    const __half* __restrict__ A, const __half* __restrict__ Bt, float* __restrict__ C) {
    extern __shared__ __half hs[];
    // layout: A0 | B0 | A1 | B1, each 128*H_ST halves

    int bm = blockIdx.y, bn = blockIdx.x;
    int tid  = threadIdx.x;
    int warp = tid >> 5, lane = tid & 31;
    int wm = warp >> 2, wn = warp & 3;
    int g = lane >> 2, tg = lane & 3;

    float acc[4][4][4];
    #pragma unroll
    for (int mt = 0; mt < 4; mt++)
        #pragma unroll
        for (int nt = 0; nt < 4; nt++)
            #pragma unroll
            for (int r = 0; r < 4; r++) acc[mt][nt][r] = 0.f;

    const __half* Ab = A + (size_t)(bm * 128) * D_DIM;
    const __half* Bb = Bt + (size_t)(bn * 128) * D_DIM;

    int lrow = tid >> 1;                 // 0..127
    int cbase = (tid & 1) * 4;           // chunk base (each chunk = 8 halves = 16B)

    auto load_stage = [&](int s, int k0) {
        __half* As = hs + s * 2 * H_MAT;
        __half* Bs = As + H_MAT;
        #pragma unroll
        for (int c = 0; c < 4; c++) {
            int ch = cbase + c;
            cp16(&As[lrow * H_ST + ch * 8], Ab + (size_t)lrow * D_DIM + k0 + ch * 8);
            cp16(&Bs[lrow * H_ST + ch * 8], Bb + (size_t)lrow * D_DIM + k0 + ch * 8);
        }
    };

    load_stage(0, 0);
    cp_commit();

    const int NT = D_DIM / HKT;   // 16
    for (int t = 0; t < NT; t++) {
        __half* Ac = hs + (t & 1) * 2 * H_MAT;
        __half* Bc = Ac + H_MAT;
        if (t + 1 < NT) {
            load_stage((t + 1) & 1, (t + 1) * HKT);
            cp_commit();
            asm volatile("cp.async.wait_group 1;");
        } else {
            asm volatile("cp.async.wait_group 0;");
        }
        __syncthreads();

        #pragma unroll
        for (int kk = 0; kk < 4; kk++) {          // 4 x k16 per 64-wide tile
            uint32_t bf[4][2];
            #pragma unroll
            for (int nt = 0; nt < 4; nt++) {
                int col = wn * 32 + nt * 8 + g;
                bf[nt][0] = *(uint32_t*)&Bc[col * H_ST + kk * 16 + tg * 2];
                bf[nt][1] = *(uint32_t*)&Bc[col * H_ST + kk * 16 + tg * 2 + 8];
            }
            #pragma unroll
            for (int mt = 0; mt < 4; mt++) {
                int r0 = wm * 64 + mt * 16;
                uint32_t af[4];
                af[0] = *(uint32_t*)&Ac[(r0 + g) * H_ST + kk * 16 + tg * 2];
                af[1] = *(uint32_t*)&Ac[(r0 + g + 8) * H_ST + kk * 16 + tg * 2];
                af[2] = *(uint32_t*)&Ac[(r0 + g) * H_ST + kk * 16 + tg * 2 + 8];
                af[3] = *(uint32_t*)&Ac[(r0 + g + 8) * H_ST + kk * 16 + tg * 2 + 8];
                #pragma unroll
                for (int nt = 0; nt < 4; nt++)
                    mma_f16(acc[mt][nt], af, bf[nt]);
            }
        }
        __syncthreads();
    }

    int row0 = bm * 128 + wm * 64;
    int col0 = bn * 128 + wn * 32;
    #pragma unroll
    for (int mt = 0; mt < 4; mt++)
        #pragma unroll
        for (int nt = 0; nt < 4; nt++) {
            int row = row0 + mt * 16 + g;
            int col = col0 + nt * 8 + tg * 2;
            *(float2*)(C + (size_t)row * V_DIM + col) = make_float2(acc[mt][nt][0], acc[mt][nt][1]);
            *(float2*)(C + (size_t)(row + 8) * V_DIM + col) = make_float2(acc[mt][nt][2], acc[mt][nt][3]);
        }
}

// ---------------- fused prep: beta, silu+l2norm(q), silu+l2norm(k), qk dot ----------------
__global__ void prep_k(const float* __restrict__ x, const float* __restrict__ wb,
                       float* __restrict__ q, float* __restrict__ k,
                       float* __restrict__ beta, float* __restrict__ qk) {
    __shared__ float sh0[8], sh1[8], sh2[8], sh3[8];
    int row = blockIdx.x, tid = threadIdx.x;

    const float4* xr = (const float4*)(x + (size_t)row * D_DIM);
    const float4* wr = (const float4*)wb;
    float4 xv = xr[tid], wv = wr[tid];
    float bd = xv.x * wv.x + xv.y * wv.y + xv.z * wv.z + xv.w * wv.w;
    float bsum = blockReduceSum(bd, sh0);
    if (tid == 0) beta[row] = 1.f / (1.f + expf(-bsum));

    float4* qr = (float4*)(q + (size_t)row * D_DIM);
    float4 a = qr[tid];
    a.x = silu1(a.x); a.y = silu1(a.y); a.z = silu1(a.z); a.w = silu1(a.w);
    float qs = a.x * a.x + a.y * a.y + a.z * a.z + a.w * a.w;
    float qtot = blockReduceSum(qs, sh1);
    float qrs = rsqrtf(qtot + 1e-6f);
    a.x *= qrs; a.y *= qrs; a.z *= qrs; a.w *= qrs;
    qr[tid] = a;

    float4* kr = (float4*)(k + (size_t)row * D_DIM);
    float4 b = kr[tid];
    b.x = silu1(b.x); b.y = silu1(b.y); b.z = silu1(b.z); b.w = silu1(b.w);
    float ks = b.x * b.x + b.y * b.y + b.z * b.z + b.w * b.w;
    float ktot = blockReduceSum(ks, sh2);
    float krs = rsqrtf(ktot + 1e-6f);
    b.x *= krs; b.y *= krs; b.z *= krs; b.w *= krs;
    kr[tid] = b;

    float d = a.x * b.x + a.y * b.y + a.z * b.z + a.w * b.w;
    float dtot = blockReduceSum(d, sh3);
    if (tid == 0) qk[row] = dtot;
}

// ---------------- rmsnorm in place ----------------
__global__ void rmsnorm_k(float* __restrict__ x, const float* __restrict__ w) {
    __shared__ float sh[8];
    float4* xr = (float4*)(x + (size_t)blockIdx.x * D_DIM);
    float4 a = xr[threadIdx.x];
    float ss = a.x * a.x + a.y * a.y + a.z * a.z + a.w * a.w;
    float tot = blockReduceSum(ss, sh);
    float r = rsqrtf(tot * (1.f / D_DIM) + 1e-5f);
    float4 wv = ((const float4*)w)[threadIdx.x];
    a.x *= r * wv.x; a.y *= r * wv.y; a.z *= r * wv.z; a.w *= r * wv.w;
    xr[threadIdx.x] = a;
}

// ---------------- layernorm -> fp16 output ----------------
__global__ void layernorm_h(const float* __restrict__ x, const float* __restrict__ gg,
                            const float* __restrict__ bb, __half* __restrict__ xh) {
    __shared__ float sh1[8];
    __shared__ float sh2[8];
    const float4* xr = (const float4*)(x + (size_t)blockIdx.x * D_DIM);
    float4 a = xr[threadIdx.x];
    float s  = a.x + a.y + a.z + a.w;
    float ss = a.x * a.x + a.y * a.y + a.z * a.z + a.w * a.w;
    float S  = blockReduceSum(s, sh1);
    float SS = blockReduceSum(ss, sh2);
    float mu  = S * (1.f / D_DIM);
    float var = SS * (1.f / D_DIM) - mu * mu;
    float r = rsqrtf(var + 1e-5f);
    float4 gv = ((const float4*)gg)[threadIdx.x];
    float4 bv = ((const float4*)bb)[threadIdx.x];
    float o0 = (a.x - mu) * r * gv.x + bv.x;
    float o1 = (a.y - mu) * r * gv.y + bv.y;
    float o2 = (a.z - mu) * r * gv.z + bv.z;
    float o3 = (a.w - mu) * r * gv.w + bv.w;
    __half2 h01 = __floats2half2_rn(o0, o1);
    __half2 h23 = __floats2half2_rn(o2, o3);
    uint2 packed = make_uint2(*reinterpret_cast<uint32_t*>(&h01), *reinterpret_cast<uint32_t*>(&h23));
    *(uint2*)&xh[(size_t)blockIdx.x * D_DIM + threadIdx.x * 4] = packed;
}

// ---------------- delta-rule scan (R4 version, known good) ----------------
__global__ __launch_bounds__(256) void delta_scan(
    const float* __restrict__ q, const float* __restrict__ k,
    const float* __restrict__ v, const float* __restrict__ beta,
    const float* __restrict__ qk, float* __restrict__ o) {
    __shared__ float sk[1024];
    __shared__ float sq[1024];
    __shared__ float part[16 * 132];
    __shared__ float tot[16];

    int tid = threadIdx.x;
    int b = blockIdx.x >> 7;
    int ebase = (blockIdx.x & 127) * 8;
    int cg = tid >> 7;
    int rg = tid & 127;
    int d0 = rg * 8;
    int e0 = ebase + cg * 4;

    float2 S[4][4];
    #pragma unroll
    for (int r = 0; r < 4; r++)
        #pragma unroll
        for (int c = 0; c < 4; c++) S[r][c] = make_float2(0.f, 0.f);

    const float* qb = q + (size_t)b * S_DIM * D_DIM;
    const float* kb = k + (size_t)b * S_DIM * D_DIM;
    const float* vb = v + (size_t)b * S_DIM * D_DIM;
    const float* betab = beta + b * S_DIM;
    const float* qkb   = qk + b * S_DIM;
    float* ob = o + (size_t)b * S_DIM * D_DIM;

    int gj = tid >> 4, sl = tid & 15;

    for (int t = 0; t < S_DIM; t++) {
        ((float4*)sk)[tid] = ((const float4*)(kb + (size_t)t * D_DIM))[tid];
        ((float4*)sq)[tid] = ((const float4*)(qb + (size_t)t * D_DIM))[tid];
        __syncthreads();

        float4 kA = *(float4*)(sk + d0);
        float4 kB = *(float4*)(sk + d0 + 4);
        float4 qA = *(float4*)(sq + d0);
        float4 qB = *(float4*)(sq + d0 + 4);
        float2 kv[4] = {{kA.x, kA.y}, {kA.z, kA.w}, {kB.x, kB.y}, {kB.z, kB.w}};
        float2 qv[4] = {{qA.x, qA.y}, {qA.z, qA.w}, {qB.x, qB.y}, {qB.z, qB.w}};

        float2 ks2[4], qs2[4];
        #pragma unroll
        for (int c = 0; c < 4; c++) { ks2[c] = make_float2(0.f, 0.f); qs2[c] = make_float2(0.f, 0.f); }
        #pragma unroll
        for (int c = 0; c < 4; c++)
            #pragma unroll
            for (int r = 0; r < 4; r++) {
                ks2[c] = ffma2(kv[r], S[r][c], ks2[c]);
                qs2[c] = ffma2(qv[r], S[r][c], qs2[c]);
            }
        #pragma unroll
        for (int c = 0; c < 4; c++) {
            part[(cg * 8 + c) * 132 + rg]     = ks2[c].x + ks2[c].y;
            part[(cg * 8 + 4 + c) * 132 + rg] = qs2[c].x + qs2[c].y;
        }
        __syncthreads();

        {
            const float* pg = part + gj * 132;
            float ps = 0.f;
            #pragma unroll
            for (int i = 0; i < 8; i++) ps += pg[sl + 16 * i];
            #pragma unroll
            for (int off = 8; off; off >>= 1) ps += __shfl_down_sync(0xffffffffu, ps, off, 16);
            if (sl == 0) tot[gj] = ps;
        }
        __syncthreads();

        float be  = betab[t];
        float qkt = qkb[t];
        float cc[4];
        #pragma unroll
        for (int c = 0; c < 4; c++) {
            float ksv = tot[cg * 8 + c];
            float vv  = __ldg(vb + (size_t)t * D_DIM + e0 + c);
            cc[c] = be * (vv - ksv);
            if (rg == 0) ob[(size_t)t * D_DIM + e0 + c] = tot[cg * 8 + 4 + c] + qkt * cc[c];
        }
        #pragma unroll
        for (int c = 0; c < 4; c++) {
            float2 c2 = make_float2(cc[c], cc[c]);
            #pragma unroll
            for (int r = 0; r < 4; r++) S[r][c] = ffma2(kv[r], c2, S[r][c]);
        }
        __syncthreads();
    }
}

// ---------------- host orchestration ----------------
extern "C" void kernel_launch(void* const* d_in, const int* in_sizes, int n_in,
                              void* d_out, int out_size) {
    const int*   tokens = (const int*)d_in[0];
    const float* emb    = (const float*)d_in[1];
    const float* Wq     = (const float*)d_in[2];
    const float* Wk     = (const float*)d_in[3];
    const float* Wv     = (const float*)d_in[4];
    const float* Wb     = (const float*)d_in[5];
    const float* Wo     = (const float*)d_in[6];
    const float* rms_w  = (const float*)d_in[7];
    const float* ln_g   = (const float*)d_in[8];
    const float* ln_b   = (const float*)d_in[9];
    const float* head_w = (const float*)d_in[10];
    float* out = (float*)d_out;

    float *x, *qb, *kb, *vb, *ob, *betab, *qkb;
    __half *xh, *wt;
    cudaGetSymbolAddress((void**)&x, g_x);
    cudaGetSymbolAddress((void**)&qb, g_q);
    cudaGetSymbolAddress((void**)&kb, g_k);
    cudaGetSymbolAddress((void**)&vb, g_v);
    cudaGetSymbolAddress((void**)&ob, g_o);
    cudaGetSymbolAddress((void**)&betab, g_beta);
    cudaGetSymbolAddress((void**)&qkb, g_qk);
    cudaGetSymbolAddress((void**)&xh, g_xh);
    cudaGetSymbolAddress((void**)&wt, g_wt);

    cudaFuncSetAttribute(gemm_mm,       cudaFuncAttributeMaxDynamicSharedMemorySize, GEMM_SMEM_BYTES);
    cudaFuncSetAttribute(gemm_qkv,      cudaFuncAttributeMaxDynamicSharedMemorySize, GEMM_SMEM_BYTES);
    cudaFuncSetAttribute(gemm_head_f16, cudaFuncAttributeMaxDynamicSharedMemorySize, HEAD_SMEM_BYTES);

    embed_k<<<NROWS, 256>>>(tokens, emb, x);
    transpose_h<<<dim3(V_DIM / 32, D_DIM / 32), dim3(32, 8)>>>(head_w, wt);

    dim3 g1(D_DIM / 128, NROWS / 128);
    dim3 gqkv(D_DIM / 128, NROWS / 128, 3);
    for (int l = 0; l < L_DIM; l++) {
        const float* wq = Wq + (size_t)l * D_DIM * D_DIM;
        const float* wk = Wk + (size_t)l * D_DIM * D_DIM;
        const float* wv = Wv + (size_t)l * D_DIM * D_DIM;
        const float* wb = Wb + (size_t)l * D_DIM;
        const float* wo = Wo + (size_t)l * D_DIM * D_DIM;
        const float* rw = rms_w + (size_t)l * D_DIM;

        gemm_qkv<<<gqkv, 256, GEMM_SMEM_BYTES>>>(x, wq, wk, wv, qb, kb, vb);
        prep_k<<<NROWS, 256>>>(x, wb, qb, kb, betab, qkb);
        delta_scan<<<256, 256>>>(qb, kb, vb, betab, qkb, ob);
        rmsnorm_k<<<NROWS, 256>>>(ob, rw);
        gemm_mm<<<g1, 256, GEMM_SMEM_BYTES>>>(ob, wo, x, NROWS, D_DIM, D_DIM);
    }
    layernorm_h<<<NROWS, 256>>>(x, ln_g, ln_b, xh);

    dim3 g2(V_DIM / 128, NROWS / 128);   // (250,16)
    gemm_head_f16<<<g2, 256, HEAD_SMEM_BYTES>>>(xh, wt, out);
}

// round 16
// speedup vs baseline: 1.4261x; 1.2012x over previous
#include <cuda_runtime.h>
#include <cuda_bf16.h>
#include <cuda_fp16.h>
#include <cstdint>
#include <math.h>

#define D_DIM 1024
#define B_DIM 2
#define S_DIM 1024
#define NROWS (B_DIM * S_DIM)   // 2048
#define NPAIRS (NROWS / 2)
#define L_DIM 2
#define V_DIM 32000

// GEMM smem geometry (floats), 2-stage pipeline, 128x128 tiles
#define A_STRIDE 36
#define B_STRIDE 136
#define A_TILE (128 * A_STRIDE)
#define B_TILE (32 * B_STRIDE)
#define GEMM_SMEM_BYTES (2 * (A_TILE + B_TILE) * 4)   // 71680

// fp16 head GEMM geometry
#define HKT 64
#define H_ST 72
#define H_MAT (128 * H_ST)
#define HEAD_SMEM_BYTES (2 * 2 * H_MAT * 2)  // 73728

// ---------------- scratch (device globals; no allocation allowed) ----------------
__device__ float g_x[NROWS * D_DIM];
__device__ float g_q[NROWS * D_DIM];
__device__ float g_k[NROWS * D_DIM];
__device__ float g_v[NROWS * D_DIM];
__device__ float g_o[NROWS * D_DIM];
__device__ float g_beta[NROWS];
__device__ float g_qk[NROWS];
__device__ float g_kk[NPAIRS];   // k_{2i} . k_{2i+1}
__device__ float g_kq[NPAIRS];   // k_{2i} . q_{2i+1}
__device__ __half g_xh[NROWS * D_DIM];
__device__ __half g_wt[(size_t)V_DIM * D_DIM];

// ---------------- helpers ----------------
__device__ __forceinline__ float2 ffma2(float2 a, float2 b, float2 c) {
    float2 d;
    asm("fma.rn.f32x2 %0, %1, %2, %3;"
        : "=l"(reinterpret_cast<unsigned long long &>(d))
        : "l"(reinterpret_cast<unsigned long long &>(a)),
          "l"(reinterpret_cast<unsigned long long &>(b)),
          "l"(reinterpret_cast<unsigned long long &>(c)));
    return d;
}

__device__ __forceinline__ void mma_bf16(float* c, const uint32_t* a, const uint32_t* b) {
    asm volatile(
        "mma.sync.aligned.m16n8k16.row.col.f32.bf16.bf16.f32 "
        "{%0,%1,%2,%3}, {%4,%5,%6,%7}, {%8,%9}, {%0,%1,%2,%3};"
        : "+f"(c[0]), "+f"(c[1]), "+f"(c[2]), "+f"(c[3])
        : "r"(a[0]), "r"(a[1]), "r"(a[2]), "r"(a[3]), "r"(b[0]), "r"(b[1]));
}

__device__ __forceinline__ void mma_f16(float* c, const uint32_t* a, const uint32_t* b) {
    asm volatile(
        "mma.sync.aligned.m16n8k16.row.col.f32.f16.f16.f32 "
        "{%0,%1,%2,%3}, {%4,%5,%6,%7}, {%8,%9}, {%0,%1,%2,%3};"
        : "+f"(c[0]), "+f"(c[1]), "+f"(c[2]), "+f"(c[3])
        : "r"(a[0]), "r"(a[1]), "r"(a[2]), "r"(a[3]), "r"(b[0]), "r"(b[1]));
}

__device__ __forceinline__ void split_pair(float f0, float f1, uint32_t& hi, uint32_t& lo) {
    __nv_bfloat162 h2 = __floats2bfloat162_rn(f0, f1);
    float r0 = f0 - __low2float(h2);
    float r1 = f1 - __high2float(h2);
    __nv_bfloat162 l2 = __floats2bfloat162_rn(r0, r1);
    hi = *reinterpret_cast<uint32_t*>(&h2);
    lo = *reinterpret_cast<uint32_t*>(&l2);
}

__device__ __forceinline__ void cp16(void* dst, const void* src) {
    uint32_t d = (uint32_t)__cvta_generic_to_shared(dst);
    asm volatile("cp.async.cg.shared.global [%0], [%1], 16;" :: "r"(d), "l"(src));
}
__device__ __forceinline__ void cp_commit() {
    asm volatile("cp.async.commit_group;");
}

__device__ __forceinline__ float silu1(float x) { return x / (1.f + expf(-x)); }
__device__ __forceinline__ float4 silu4(float4 a) {
    a.x = silu1(a.x); a.y = silu1(a.y); a.z = silu1(a.z); a.w = silu1(a.w);
    return a;
}
__device__ __forceinline__ float dot4(float4 a, float4 b) {
    return a.x * b.x + a.y * b.y + a.z * b.z + a.w * b.w;
}
__device__ __forceinline__ float4 scale4(float4 a, float s) {
    a.x *= s; a.y *= s; a.z *= s; a.w *= s;
    return a;
}

__device__ __forceinline__ float blockReduceSum(float v, float* sh) {
    #pragma unroll
    for (int o = 16; o; o >>= 1) v += __shfl_xor_sync(0xffffffffu, v, o);
    int w = threadIdx.x >> 5;
    if ((threadIdx.x & 31) == 0) sh[w] = v;
    __syncthreads();
    if (threadIdx.x == 0) {
        float s = sh[0];
        #pragma unroll
        for (int i = 1; i < 8; i++) s += sh[i];
        sh[0] = s;
    }
    __syncthreads();
    return sh[0];
}

// batched block reduce: N values per thread reduced across block; result in v[] for all threads
template <int N>
__device__ __forceinline__ void blockReduceN(float* v, float* sh /* 8*N */) {
    #pragma unroll
    for (int i = 0; i < N; i++)
        #pragma unroll
        for (int o = 16; o; o >>= 1) v[i] += __shfl_xor_sync(0xffffffffu, v[i], o);
    int w = threadIdx.x >> 5;
    if ((threadIdx.x & 31) == 0)
        #pragma unroll
        for (int i = 0; i < N; i++) sh[w * N + i] = v[i];
    __syncthreads();
    #pragma unroll
    for (int i = 0; i < N; i++) {
        float s = 0.f;
        #pragma unroll
        for (int j = 0; j < 8; j++) s += sh[j * N + i];
        v[i] = s;
    }
    __syncthreads();
}

// ---------------- embedding gather ----------------
__global__ void embed_k(const int* __restrict__ tokens, const float* __restrict__ emb,
                        float* __restrict__ x) {
    int row = blockIdx.x;
    int tok = tokens[row];
    ((float4*)(x + (size_t)row * D_DIM))[threadIdx.x] =
        ((const float4*)(emb + (size_t)tok * D_DIM))[threadIdx.x];
}

// ---------------- transpose head_w -> fp16 Wt[N][K] ----------------
__global__ void transpose_h(const float* __restrict__ W, __half* __restrict__ Wt) {
    __shared__ float tile[32][33];
    int n0 = blockIdx.x * 32, k0 = blockIdx.y * 32;
    int tx = threadIdx.x, ty = threadIdx.y;
    #pragma unroll
    for (int i = ty; i < 32; i += 8)
        tile[i][tx] = W[(size_t)(k0 + i) * V_DIM + n0 + tx];
    __syncthreads();
    #pragma unroll
    for (int i = ty; i < 32; i += 8)
        Wt[(size_t)(n0 + i) * D_DIM + k0 + tx] = __float2half(tile[tx][i]);
}

// ---------------- GEMM core 128x128 (2-stage cp.async, bf16 hi/lo 3-product) ----------------
template <bool SILU>
__device__ __forceinline__ void gemm_body(
    const float* __restrict__ A, const float* __restrict__ B, float* __restrict__ C,
    int N, int K, int bm, int bn, float* sm) {

    int tid  = threadIdx.x;
    int warp = tid >> 5, lane = tid & 31;
    int wm = warp >> 2, wn = warp & 3;
    int g = lane >> 2, tg = lane & 3;

    float acc[4][4][4];
    #pragma unroll
    for (int mt = 0; mt < 4; mt++)
        #pragma unroll
        for (int nt = 0; nt < 4; nt++)
            #pragma unroll
            for (int r = 0; r < 4; r++) acc[mt][nt][r] = 0.f;

    const float* Ab = A + (size_t)(bm * 128) * K;
    const float* Bb = B + bn * 128;

    int arow = tid >> 3;
    int acol = (tid & 7) * 4;
    int brow = tid >> 5;
    int bcol = (tid & 31) * 4;

    const int NT = K >> 5;

    {
        float* A0 = sm;
        float* B0 = sm + 2 * A_TILE;
        #pragma unroll
        for (int p = 0; p < 4; p++) {
            int r = arow + p * 32;
            cp16(&A0[r * A_STRIDE + acol], Ab + (size_t)r * K + acol);
        }
        #pragma unroll
        for (int p = 0; p < 4; p++) {
            int r = brow + p * 8;
            cp16(&B0[r * B_STRIDE + bcol], Bb + (size_t)r * N + bcol);
        }
        cp_commit();
    }

    for (int t = 0; t < NT; t++) {
        float* Ac = sm + (t & 1) * A_TILE;
        float* Bc = sm + 2 * A_TILE + (t & 1) * B_TILE;
        if (t + 1 < NT) {
            float* An = sm + ((t + 1) & 1) * A_TILE;
            float* Bn = sm + 2 * A_TILE + ((t + 1) & 1) * B_TILE;
            int k0 = (t + 1) * 32;
            #pragma unroll
            for (int p = 0; p < 4; p++) {
                int r = arow + p * 32;
                cp16(&An[r * A_STRIDE + acol], Ab + (size_t)r * K + k0 + acol);
            }
            #pragma unroll
            for (int p = 0; p < 4; p++) {
                int r = brow + p * 8;
                cp16(&Bn[r * B_STRIDE + bcol], Bb + (size_t)(k0 + r) * N + bcol);
            }
            cp_commit();
            asm volatile("cp.async.wait_group 1;");
        } else {
            asm volatile("cp.async.wait_group 0;");
        }
        __syncthreads();

        #pragma unroll
        for (int kk = 0; kk < 2; kk++) {
            uint32_t bh[4][2], bl[4][2];
            #pragma unroll
            for (int nt = 0; nt < 4; nt++) {
                int col = wn * 32 + nt * 8 + g;
                #pragma unroll
                for (int h = 0; h < 2; h++) {
                    int krow = kk * 16 + tg * 2 + h * 8;
                    float f0 = Bc[krow * B_STRIDE + col];
                    float f1 = Bc[(krow + 1) * B_STRIDE + col];
                    split_pair(f0, f1, bh[nt][h], bl[nt][h]);
                }
            }
            #pragma unroll
            for (int mt = 0; mt < 4; mt++) {
                int rbase = (wm * 64 + mt * 16) * A_STRIDE + kk * 16 + tg * 2;
                float2 p0 = *(float2*)&Ac[rbase + g * A_STRIDE];
                float2 p1 = *(float2*)&Ac[rbase + (g + 8) * A_STRIDE];
                float2 p2 = *(float2*)&Ac[rbase + g * A_STRIDE + 8];
                float2 p3 = *(float2*)&Ac[rbase + (g + 8) * A_STRIDE + 8];
                uint32_t ah[4], al[4];
                split_pair(p0.x, p0.y, ah[0], al[0]);
                split_pair(p1.x, p1.y, ah[1], al[1]);
                split_pair(p2.x, p2.y, ah[2], al[2]);
                split_pair(p3.x, p3.y, ah[3], al[3]);
                #pragma unroll
                for (int nt = 0; nt < 4; nt++) {
                    mma_bf16(acc[mt][nt], ah, bl[nt]);
                    mma_bf16(acc[mt][nt], al, bh[nt]);
                    mma_bf16(acc[mt][nt], ah, bh[nt]);
                }
            }
        }
        __syncthreads();
    }

    int row0 = bm * 128 + wm * 64;
    int col0 = bn * 128 + wn * 32;
    #pragma unroll
    for (int mt = 0; mt < 4; mt++)
        #pragma unroll
        for (int nt = 0; nt < 4; nt++) {
            int row = row0 + mt * 16 + g;
            int col = col0 + nt * 8 + tg * 2;
            float v0 = acc[mt][nt][0], v1 = acc[mt][nt][1];
            float v2 = acc[mt][nt][2], v3 = acc[mt][nt][3];
            if (SILU) { v0 = silu1(v0); v1 = silu1(v1); v2 = silu1(v2); v3 = silu1(v3); }
            *(float2*)(C + (size_t)row * N + col) = make_float2(v0, v1);
            *(float2*)(C + (size_t)(row + 8) * N + col) = make_float2(v2, v3);
        }
}

__global__ __launch_bounds__(256, 2) void gemm_mm(
    const float* __restrict__ A, const float* __restrict__ B, float* __restrict__ C,
    int M, int N, int K) {
    extern __shared__ float sm[];
    gemm_body<false>(A, B, C, N, K, blockIdx.y, blockIdx.x, sm);
}

__global__ __launch_bounds__(256, 2) void gemm_qkv(
    const float* __restrict__ X,
    const float* __restrict__ Wq, const float* __restrict__ Wk, const float* __restrict__ Wv,
    float* __restrict__ Q, float* __restrict__ Ko, float* __restrict__ Vo) {
    extern __shared__ float sm[];
    int z = blockIdx.z;
    const float* B = (z == 0) ? Wq : (z == 1) ? Wk : Wv;
    float* C = (z == 0) ? Q : (z == 1) ? Ko : Vo;
    if (z == 2)
        gemm_body<true>(X, B, C, D_DIM, D_DIM, blockIdx.y, blockIdx.x, sm);
    else
        gemm_body<false>(X, B, C, D_DIM, D_DIM, blockIdx.y, blockIdx.x, sm);
}

// ---------------- fp16 head GEMM ----------------
__global__ __launch_bounds__(256, 2) void gemm_head_f16(
    const __half* __restrict__ A, const __half* __restrict__ Bt, float* __restrict__ C) {
    extern __shared__ __half hs[];

    int bm = blockIdx.y, bn = blockIdx.x;
    int tid  = threadIdx.x;
    int warp = tid >> 5, lane = tid & 31;
    int wm = warp >> 2, wn = warp & 3;
    int g = lane >> 2, tg = lane & 3;

    float acc[4][4][4];
    #pragma unroll
    for (int mt = 0; mt < 4; mt++)
        #pragma unroll
        for (int nt = 0; nt < 4; nt++)
            #pragma unroll
            for (int r = 0; r < 4; r++) acc[mt][nt][r] = 0.f;

    const __half* Ab = A + (size_t)(bm * 128) * D_DIM;
    const __half* Bb = Bt + (size_t)(bn * 128) * D_DIM;

    int lrow = tid >> 1;
    int cbase = (tid & 1) * 4;

    auto load_stage = [&](int s, int k0) {
        __half* As = hs + s * 2 * H_MAT;
        __half* Bs = As + H_MAT;
        #pragma unroll
        for (int c = 0; c < 4; c++) {
            int ch = cbase + c;
            cp16(&As[lrow * H_ST + ch * 8], Ab + (size_t)lrow * D_DIM + k0 + ch * 8);
            cp16(&Bs[lrow * H_ST + ch * 8], Bb + (size_t)lrow * D_DIM + k0 + ch * 8);
        }
    };

    load_stage(0, 0);
    cp_commit();

    const int NT = D_DIM / HKT;
    for (int t = 0; t < NT; t++) {
        __half* Ac = hs + (t & 1) * 2 * H_MAT;
        __half* Bc = Ac + H_MAT;
        if (t + 1 < NT) {
            load_stage((t + 1) & 1, (t + 1) * HKT);
            cp_commit();
            asm volatile("cp.async.wait_group 1;");
        } else {
            asm volatile("cp.async.wait_group 0;");
        }
        __syncthreads();

        #pragma unroll
        for (int kk = 0; kk < 4; kk++) {
            uint32_t bf[4][2];
            #pragma unroll
            for (int nt = 0; nt < 4; nt++) {
                int col = wn * 32 + nt * 8 + g;
                bf[nt][0] = *(uint32_t*)&Bc[col * H_ST + kk * 16 + tg * 2];
                bf[nt][1] = *(uint32_t*)&Bc[col * H_ST + kk * 16 + tg * 2 + 8];
            }
            #pragma unroll
            for (int mt = 0; mt < 4; mt++) {
                int r0 = wm * 64 + mt * 16;
                uint32_t af[4];
                af[0] = *(uint32_t*)&Ac[(r0 + g) * H_ST + kk * 16 + tg * 2];
                af[1] = *(uint32_t*)&Ac[(r0 + g + 8) * H_ST + kk * 16 + tg * 2];
                af[2] = *(uint32_t*)&Ac[(r0 + g) * H_ST + kk * 16 + tg * 2 + 8];
                af[3] = *(uint32_t*)&Ac[(r0 + g + 8) * H_ST + kk * 16 + tg * 2 + 8];
                #pragma unroll
                for (int nt = 0; nt < 4; nt++)
                    mma_f16(acc[mt][nt], af, bf[nt]);
            }
        }
        __syncthreads();
    }

    int row0 = bm * 128 + wm * 64;
    int col0 = bn * 128 + wn * 32;
    #pragma unroll
    for (int mt = 0; mt < 4; mt++)
        #pragma unroll
        for (int nt = 0; nt < 4; nt++) {
            int row = row0 + mt * 16 + g;
            int col = col0 + nt * 8 + tg * 2;
            *(float2*)(C + (size_t)row * V_DIM + col) = make_float2(acc[mt][nt][0], acc[mt][nt][1]);
            *(float2*)(C + (size_t)(row + 8) * V_DIM + col) = make_float2(acc[mt][nt][2], acc[mt][nt][3]);
        }
}

// ---------------- prep2: pairwise prep (beta, norms, qk) + cross-dots kk,kq ----------------
// One block per row PAIR (r0=2p, r1=2p+1).
__global__ void prep2_k(const float* __restrict__ x, const float* __restrict__ wb,
                        float* __restrict__ q, float* __restrict__ k,
                        float* __restrict__ beta, float* __restrict__ qk,
                        float* __restrict__ kkp, float* __restrict__ kqp) {
    __shared__ float sh[8 * 6];
    int p = blockIdx.x;
    int r0 = p * 2, r1 = r0 + 1;
    int tid = threadIdx.x;

    float4 wv = ((const float4*)wb)[tid];
    float4 x0 = ((const float4*)(x + (size_t)r0 * D_DIM))[tid];
    float4 x1 = ((const float4*)(x + (size_t)r1 * D_DIM))[tid];
    float4* q0p = (float4*)(q + (size_t)r0 * D_DIM);
    float4* q1p = (float4*)(q + (size_t)r1 * D_DIM);
    float4* k0p = (float4*)(k + (size_t)r0 * D_DIM);
    float4* k1p = (float4*)(k + (size_t)r1 * D_DIM);
    float4 q0 = silu4(q0p[tid]);
    float4 q1 = silu4(q1p[tid]);
    float4 k0 = silu4(k0p[tid]);
    float4 k1 = silu4(k1p[tid]);

    float red[6];
    red[0] = dot4(x0, wv);
    red[1] = dot4(x1, wv);
    red[2] = dot4(q0, q0);
    red[3] = dot4(q1, q1);
    red[4] = dot4(k0, k0);
    red[5] = dot4(k1, k1);
    blockReduceN<6>(red, sh);

    if (tid == 0) {
        beta[r0] = 1.f / (1.f + expf(-red[0]));
        beta[r1] = 1.f / (1.f + expf(-red[1]));
    }
    q0 = scale4(q0, rsqrtf(red[2] + 1e-6f));
    q1 = scale4(q1, rsqrtf(red[3] + 1e-6f));
    k0 = scale4(k0, rsqrtf(red[4] + 1e-6f));
    k1 = scale4(k1, rsqrtf(red[5] + 1e-6f));
    q0p[tid] = q0; q1p[tid] = q1; k0p[tid] = k0; k1p[tid] = k1;

    float red2[4];
    red2[0] = dot4(q0, k0);
    red2[1] = dot4(q1, k1);
    red2[2] = dot4(k0, k1);
    red2[3] = dot4(k0, q1);
    blockReduceN<4>(red2, sh);
    if (tid == 0) {
        qk[r0] = red2[0];
        qk[r1] = red2[1];
        kkp[p] = red2[2];
        kqp[p] = red2[3];
    }
}

// ---------------- rmsnorm in place ----------------
__global__ void rmsnorm_k(float* __restrict__ x, const float* __restrict__ w) {
    __shared__ float sh[8];
    float4* xr = (float4*)(x + (size_t)blockIdx.x * D_DIM);
    float4 a = xr[threadIdx.x];
    float ss = a.x * a.x + a.y * a.y + a.z * a.z + a.w * a.w;
    float tot = blockReduceSum(ss, sh);
    float r = rsqrtf(tot * (1.f / D_DIM) + 1e-5f);
    float4 wv = ((const float4*)w)[threadIdx.x];
    a.x *= r * wv.x; a.y *= r * wv.y; a.z *= r * wv.z; a.w *= r * wv.w;
    xr[threadIdx.x] = a;
}

// ---------------- layernorm -> fp16 output ----------------
__global__ void layernorm_h(const float* __restrict__ x, const float* __restrict__ gg,
                            const float* __restrict__ bb, __half* __restrict__ xh) {
    __shared__ float sh1[8];
    __shared__ float sh2[8];
    const float4* xr = (const float4*)(x + (size_t)blockIdx.x * D_DIM);
    float4 a = xr[threadIdx.x];
    float s  = a.x + a.y + a.z + a.w;
    float ss = a.x * a.x + a.y * a.y + a.z * a.z + a.w * a.w;
    float S  = blockReduceSum(s, sh1);
    float SS = blockReduceSum(ss, sh2);
    float mu  = S * (1.f / D_DIM);
    float var = SS * (1.f / D_DIM) - mu * mu;
    float r = rsqrtf(var + 1e-5f);
    float4 gv = ((const float4*)gg)[threadIdx.x];
    float4 bv = ((const float4*)bb)[threadIdx.x];
    float o0 = (a.x - mu) * r * gv.x + bv.x;
    float o1 = (a.y - mu) * r * gv.y + bv.y;
    float o2 = (a.z - mu) * r * gv.z + bv.z;
    float o3 = (a.w - mu) * r * gv.w + bv.w;
    __half2 h01 = __floats2half2_rn(o0, o1);
    __half2 h23 = __floats2half2_rn(o2, o3);
    uint2 packed = make_uint2(*reinterpret_cast<uint32_t*>(&h01), *reinterpret_cast<uint32_t*>(&h23));
    *(uint2*)&xh[(size_t)blockIdx.x * D_DIM + threadIdx.x * 4] = packed;
}

// ---------------- delta-rule scan: 2 steps per iteration, 3 barriers ----------------
// 256 blocks x 256 threads. Block: batch b = blk>>7, 8 columns.
// Partials for BOTH steps computed against S_{t-1}; corrections via precomputed
// kk = k_t.k_{t+1}, kq = k_t.q_{t+1} and qk (per token) from prep2.
__global__ __launch_bounds__(256, 2) void delta_scan2(
    const float* __restrict__ q, const float* __restrict__ k,
    const float* __restrict__ v, const float* __restrict__ beta,
    const float* __restrict__ qk, const float* __restrict__ kkp,
    const float* __restrict__ kqp, float* __restrict__ o) {
    __shared__ float sk0[1024], sq0[1024], sk1[1024], sq1[1024];
    __shared__ float part[32 * 136];
    __shared__ float tot[32];

    int tid = threadIdx.x;
    int b = blockIdx.x >> 7;
    int ebase = (blockIdx.x & 127) * 8;
    int cg = tid >> 7;
    int rg = tid & 127;
    int d0 = rg * 8;
    int e0 = ebase + cg * 4;

    float2 S[4][4];
    #pragma unroll
    for (int r = 0; r < 4; r++)
        #pragma unroll
        for (int c = 0; c < 4; c++) S[r][c] = make_float2(0.f, 0.f);

    const float* qb = q + (size_t)b * S_DIM * D_DIM;
    const float* kb = k + (size_t)b * S_DIM * D_DIM;
    const float* vb = v + (size_t)b * S_DIM * D_DIM;
    const float* betab = beta + b * S_DIM;
    const float* qkb   = qk + b * S_DIM;
    const float* kkb   = kkp + b * (S_DIM / 2);
    const float* kqb   = kqp + b * (S_DIM / 2);
    float* ob = o + (size_t)b * S_DIM * D_DIM;

    int gj = tid >> 3, sl = tid & 7;   // 32 reduce groups x 8 threads

    for (int it = 0; it < S_DIM / 2; it++) {
        size_t off0 = (size_t)(2 * it) * D_DIM;

        ((float4*)sk0)[tid] = ((const float4*)(kb + off0))[tid];
        ((float4*)sq0)[tid] = ((const float4*)(qb + off0))[tid];
        ((float4*)sk1)[tid] = ((const float4*)(kb + off0 + D_DIM))[tid];
        ((float4*)sq1)[tid] = ((const float4*)(qb + off0 + D_DIM))[tid];
        __syncthreads();   // B1: tiles staged (also fences prior-iter partial reads of sk/sq)

        float4 t4;
        float2 kv0[4], qv0[4], kv1[4], qv1[4];
        t4 = *(float4*)(sk0 + d0);     kv0[0] = {t4.x, t4.y}; kv0[1] = {t4.z, t4.w};
        t4 = *(float4*)(sk0 + d0 + 4); kv0[2] = {t4.x, t4.y}; kv0[3] = {t4.z, t4.w};
        t4 = *(float4*)(sq0 + d0);     qv0[0] = {t4.x, t4.y}; qv0[1] = {t4.z, t4.w};
        t4 = *(float4*)(sq0 + d0 + 4); qv0[2] = {t4.x, t4.y}; qv0[3] = {t4.z, t4.w};
        t4 = *(float4*)(sk1 + d0);     kv1[0] = {t4.x, t4.y}; kv1[1] = {t4.z, t4.w};
        t4 = *(float4*)(sk1 + d0 + 4); kv1[2] = {t4.x, t4.y}; kv1[3] = {t4.z, t4.w};
        t4 = *(float4*)(sq1 + d0);     qv1[0] = {t4.x, t4.y}; qv1[1] = {t4.z, t4.w};
        t4 = *(float4*)(sq1 + d0 + 4); qv1[2] = {t4.x, t4.y}; qv1[3] = {t4.z, t4.w};

        #pragma unroll
        for (int c = 0; c < 4; c++) {
            float2 a0 = {0.f, 0.f}, a1 = {0.f, 0.f}, a2 = {0.f, 0.f}, a3 = {0.f, 0.f};
            #pragma unroll
            for (int r = 0; r < 4; r++) {
                a0 = ffma2(kv0[r], S[r][c], a0);
                a1 = ffma2(qv0[r], S[r][c], a1);
                a2 = ffma2(kv1[r], S[r][c], a2);
                a3 = ffma2(qv1[r], S[r][c], a3);
            }
            int rw = (cg * 4 + c) * 4;
            part[(rw + 0) * 136 + rg] = a0.x + a0.y;
            part[(rw + 1) * 136 + rg] = a1.x + a1.y;
            part[(rw + 2) * 136 + rg] = a2.x + a2.y;
            part[(rw + 3) * 136 + rg] = a3.x + a3.y;
        }
        __syncthreads();   // B2: partials visible

        {
            const float* pg = part + gj * 136;
            float ps = 0.f;
            #pragma unroll
            for (int i = 0; i < 16; i++) ps += pg[sl + 8 * i];
            ps += __shfl_down_sync(0xffffffffu, ps, 4, 8);
            ps += __shfl_down_sync(0xffffffffu, ps, 2, 8);
            ps += __shfl_down_sync(0xffffffffu, ps, 1, 8);
            if (sl == 0) tot[gj] = ps;
        }
        __syncthreads();   // B3: tot visible

        float be0 = __ldg(betab + 2 * it), be1 = __ldg(betab + 2 * it + 1);
        float qkv0 = __ldg(qkb + 2 * it), qkv1 = __ldg(qkb + 2 * it + 1);
        float kkv = __ldg(kkb + it), kqv = __ldg(kqb + it);
        float4 v0 = __ldg((const float4*)(vb + off0 + e0));
        float4 v1 = __ldg((const float4*)(vb + off0 + D_DIM + e0));
        float va0[4] = {v0.x, v0.y, v0.z, v0.w};
        float va1[4] = {v1.x, v1.y, v1.z, v1.w};
        #pragma unroll
        for (int c = 0; c < 4; c++) {
            int rw = (cg * 4 + c) * 4;
            float c0 = be0 * (va0[c] - tot[rw + 0]);
            float c1 = be1 * (va1[c] - tot[rw + 2] - kkv * c0);
            if (rg == 0) {
                ob[off0 + e0 + c]         = tot[rw + 1] + qkv0 * c0;
                ob[off0 + D_DIM + e0 + c] = tot[rw + 3] + kqv * c0 + qkv1 * c1;
            }
            float2 cc0 = make_float2(c0, c0), cc1 = make_float2(c1, c1);
            #pragma unroll
            for (int r = 0; r < 4; r++) {
                S[r][c] = ffma2(kv0[r], cc0, S[r][c]);
                S[r][c] = ffma2(kv1[r], cc1, S[r][c]);
            }
        }
        // no trailing barrier: B1/B2 of next iteration fence all hazards
    }
}

// ---------------- host orchestration ----------------
extern "C" void kernel_launch(void* const* d_in, const int* in_sizes, int n_in,
                              void* d_out, int out_size) {
    const int*   tokens = (const int*)d_in[0];
    const float* emb    = (const float*)d_in[1];
    const float* Wq     = (const float*)d_in[2];
    const float* Wk     = (const float*)d_in[3];
    const float* Wv     = (const float*)d_in[4];
    const float* Wb     = (const float*)d_in[5];
    const float* Wo     = (const float*)d_in[6];
    const float* rms_w  = (const float*)d_in[7];
    const float* ln_g   = (const float*)d_in[8];
    const float* ln_b   = (const float*)d_in[9];
    const float* head_w = (const float*)d_in[10];
    float* out = (float*)d_out;

    float *x, *qb, *kb, *vb, *ob, *betab, *qkb, *kkp, *kqp;
    __half *xh, *wt;
    cudaGetSymbolAddress((void**)&x, g_x);
    cudaGetSymbolAddress((void**)&qb, g_q);
    cudaGetSymbolAddress((void**)&kb, g_k);
    cudaGetSymbolAddress((void**)&vb, g_v);
    cudaGetSymbolAddress((void**)&ob, g_o);
    cudaGetSymbolAddress((void**)&betab, g_beta);
    cudaGetSymbolAddress((void**)&qkb, g_qk);
    cudaGetSymbolAddress((void**)&kkp, g_kk);
    cudaGetSymbolAddress((void**)&kqp, g_kq);
    cudaGetSymbolAddress((void**)&xh, g_xh);
    cudaGetSymbolAddress((void**)&wt, g_wt);

    cudaFuncSetAttribute(gemm_mm,       cudaFuncAttributeMaxDynamicSharedMemorySize, GEMM_SMEM_BYTES);
    cudaFuncSetAttribute(gemm_qkv,      cudaFuncAttributeMaxDynamicSharedMemorySize, GEMM_SMEM_BYTES);
    cudaFuncSetAttribute(gemm_head_f16, cudaFuncAttributeMaxDynamicSharedMemorySize, HEAD_SMEM_BYTES);

    embed_k<<<NROWS, 256>>>(tokens, emb, x);   // 0

    dim3 g1(D_DIM / 128, NROWS / 128);
    dim3 gqkv(D_DIM / 128, NROWS / 128, 3);
    for (int l = 0; l < L_DIM; l++) {
        const float* wq = Wq + (size_t)l * D_DIM * D_DIM;
        const float* wk = Wk + (size_t)l * D_DIM * D_DIM;
        const float* wv = Wv + (size_t)l * D_DIM * D_DIM;
        const float* wb = Wb + (size_t)l * D_DIM;
        const float* wo = Wo + (size_t)l * D_DIM * D_DIM;
        const float* rw = rms_w + (size_t)l * D_DIM;

        gemm_qkv<<<gqkv, 256, GEMM_SMEM_BYTES>>>(x, wq, wk, wv, qb, kb, vb);        // 1
        prep2_k<<<NPAIRS, 256>>>(x, wb, qb, kb, betab, qkb, kkp, kqp);              // 2
        delta_scan2<<<256, 256>>>(qb, kb, vb, betab, qkb, kkp, kqp, ob);            // 3 <- profiled
        rmsnorm_k<<<NROWS, 256>>>(ob, rw);
        gemm_mm<<<g1, 256, GEMM_SMEM_BYTES>>>(ob, wo, x, NROWS, D_DIM, D_DIM);
    }
    transpose_h<<<dim3(V_DIM / 32, D_DIM / 32), dim3(32, 8)>>>(head_w, wt);
    layernorm_h<<<NROWS, 256>>>(x, ln_g, ln_b, xh);

    dim3 g2(V_DIM / 128, NROWS / 128);
    gemm_head_f16<<<g2, 256, HEAD_SMEM_BYTES>>>(xh, wt, out);
}